// round 10
// baseline (speedup 1.0000x reference)
#include <cuda_runtime.h>
#include <cuda_bf16.h>
#include <cstdint>

#define NPTS 80000          // 100*100*8
#define NG 1025             // 1024 gaussians + 1 synthetic "empty"
#define NC 18
#define THREADS 256
#define TILE 64
#define NSTRIP 25
#define STRIDE_STRIP 1056   // per-strip list capacity (>= NG)

// ---- device scratch (no cudaMalloc allowed) ----
// g_rec row (12 floats): [0..2]=mu [3]=rx | [4]=ry [5]=rz [6]=a00 [7]=a01 |
//                        [8]=a02 [9]=a11 [10]=a12 [11]=a22
//   a_ij carry -0.5 and off-diagonal 2x folded:
//   arg = a00 dx^2 + a11 dy^2 + a22 dz^2 + a01 dxdy + a02 dxdz + a12 dydz
// g_ft row (20 floats): opacity-folded features (+ empty channel), pads 0.
__device__ float g_rec[NG * 12];
__device__ float g_ft[NG * 20];
__device__ unsigned short g_strip[NSTRIP * STRIDE_STRIP];
__device__ int g_strip_cnt[NSTRIP];

__device__ __forceinline__ void ffma2(uint64_t& acc, uint64_t ab, uint64_t w2) {
    asm("fma.rn.f32x2 %0, %1, %2, %0;" : "+l"(acc) : "l"(ab), "l"(w2));
}
__device__ __forceinline__ uint64_t fadd2(uint64_t a, uint64_t b) {
    uint64_t r;
    asm("add.rn.f32x2 %0, %1, %2;" : "=l"(r) : "l"(a), "l"(b));
    return r;
}

// ============ Kernel A: records + features + per-bh-strip x-cull ============
__global__ __launch_bounds__(128) void precompute(
    const float* __restrict__ means,
    const float* __restrict__ opac,
    const float* __restrict__ scales,
    const float* __restrict__ rots,
    const float* __restrict__ feats,
    const float* __restrict__ empty_scalar)
{
    const int b = blockIdx.x;
    const int tid = threadIdx.x;

    if (b < 9) {
        // ---- per-gaussian record + feature staging ----
        const int i = b * 128 + tid;
        if (i >= NG) return;
        float* rc = g_rec + i * 12;
        float* ft = g_ft + i * 20;
        if (i < NG - 1) {
            float qw = __ldg(rots + i * 4 + 0), qx = __ldg(rots + i * 4 + 1);
            float qy = __ldg(rots + i * 4 + 2), qz = __ldg(rots + i * 4 + 3);
            float inv = rsqrtf(qw * qw + qx * qx + qy * qy + qz * qz);
            qw *= inv; qx *= inv; qy *= inv; qz *= inv;
            float R00 = 1.f - 2.f * (qy * qy + qz * qz);
            float R01 = 2.f * (qx * qy - qw * qz);
            float R02 = 2.f * (qx * qz + qw * qy);
            float R10 = 2.f * (qx * qy + qw * qz);
            float R11 = 1.f - 2.f * (qx * qx + qz * qz);
            float R12 = 2.f * (qy * qz - qw * qx);
            float R20 = 2.f * (qx * qz - qw * qy);
            float R21 = 2.f * (qy * qz + qw * qx);
            float R22 = 1.f - 2.f * (qx * qx + qy * qy);

            float s0 = __ldg(scales + i * 3 + 0);
            float s1 = __ldg(scales + i * 3 + 1);
            float s2 = __ldg(scales + i * 3 + 2);
            float s0q = s0 * s0, s1q = s1 * s1, s2q = s2 * s2;

            float a  = s0q * R00 * R00 + s1q * R01 * R01 + s2q * R02 * R02;
            float bb = s0q * R00 * R10 + s1q * R01 * R11 + s2q * R02 * R12;
            float c  = s0q * R00 * R20 + s1q * R01 * R21 + s2q * R02 * R22;
            float dd = s0q * R10 * R10 + s1q * R11 * R11 + s2q * R12 * R12;
            float e  = s0q * R10 * R20 + s1q * R11 * R21 + s2q * R12 * R22;
            float f  = s0q * R20 * R20 + s1q * R21 * R21 + s2q * R22 * R22;

            float det = a * (dd * f - e * e) - bb * (bb * f - e * c) + c * (bb * e - dd * c);
            float idet = 1.0f / det;

            rc[0] = __ldg(means + i * 3 + 0);
            rc[1] = __ldg(means + i * 3 + 1);
            rc[2] = __ldg(means + i * 3 + 2);
            rc[3] = 3.f * s0;
            rc[4] = 3.f * s1;
            rc[5] = 3.f * s2;
            rc[6]  = -0.5f * (dd * f - e * e) * idet;    // a00
            rc[7]  = -(c * e - bb * f) * idet;           // a01 (2x folded)
            rc[8]  = -(bb * e - c * dd) * idet;          // a02
            rc[9]  = -0.5f * (a * f - c * c) * idet;     // a11
            rc[10] = -(bb * c - a * e) * idet;           // a12
            rc[11] = -0.5f * (a * dd - bb * bb) * idet;  // a22

            const float op = __ldg(opac + i);
            const float* fs = feats + (size_t)i * (NC - 1);
            #pragma unroll
            for (int c2 = 0; c2 < NC - 1; c2++) ft[c2] = op * __ldg(fs + c2);
            ft[NC - 1] = 0.f; ft[18] = 0.f; ft[19] = 0.f;
        } else {
            rc[0] = 0.f; rc[1] = 0.f; rc[2] = 2.2f;
            rc[3] = 240.f; rc[4] = 240.f; rc[5] = 19.2f;
            rc[6]  = -0.5f / 6400.f;
            rc[7]  = 0.f; rc[8] = 0.f;
            rc[9]  = -0.5f / 6400.f;
            rc[10] = 0.f;
            rc[11] = -0.5f / 40.96f;
            #pragma unroll
            for (int c2 = 0; c2 < NC - 1; c2++) ft[c2] = 0.f;
            ft[NC - 1] = __ldg(empty_scalar);
            ft[18] = 0.f; ft[19] = 0.f;
        }
    } else {
        // ---- strip cull: x-axis test for bh strip s (reads raw inputs) ----
        const int s = b - 9;
        const float EPS = 1e-3f;
        const float bcx = (4.f * (float)s + 2.f) * 0.8f - 40.f;
        __shared__ unsigned short sl[NG];
        __shared__ int sc;
        if (tid == 0) sc = 0;
        __syncthreads();
        for (int g = tid; g < NG - 1; g += 128) {
            const float mux = __ldg(means + 3 * g);
            const float sx = __ldg(scales + 3 * g);
            if (fabsf(bcx - mux) <= 1.2f + EPS + 3.f * sx)
                sl[atomicAdd(&sc, 1)] = (unsigned short)g;
        }
        if (tid == 0) sl[atomicAdd(&sc, 1)] = (unsigned short)(NG - 1);
        __syncthreads();
        const int n = sc;
        for (int k = tid; k < n; k += 128)
            g_strip[s * STRIDE_STRIP + k] = sl[k];
        if (tid == 0) g_strip_cnt[s] = n;
    }
}

// ============ Kernel B: per-block y/z cull + copy-stage + eval ============
// Block tile: 4h x 4w x 8d = 128 points. 2 threads per point (gaussian-split).
__global__ __launch_bounds__(THREADS, 4) void voxelize(float* __restrict__ out)
{
    const int tid = threadIdx.x;
    const int pt = tid & 127;
    const int half = tid >> 7;
    const int bh = blockIdx.x, bw = blockIdx.y;
    const int dd = pt & 7;
    const int ww = (pt >> 3) & 3;
    const int hh = pt >> 5;
    const int h = 4 * bh + hh;
    const int w = 4 * bw + ww;
    const int p = h * 800 + w * 8 + dd;

    // match reference rounding
    const float px = __fadd_rn(__fmul_rn((float)h + 0.5f, 0.8f), -40.f);
    const float py = __fadd_rn(__fmul_rn((float)w + 0.5f, 0.8f), -40.f);
    const float pz = __fadd_rn(__fmul_rn((float)dd + 0.5f, 0.8f), -1.f);

    const float EPS = 1e-3f;
    const float bcy = (4.f * (float)bw + 2.f) * 0.8f - 40.f;   // half 1.2
    const float BH  = 1.2f + EPS;
    const float BHZ = 2.8f + EPS;                               // z center 2.2

    __shared__ unsigned short s_list[NG + 1];
    __shared__ int s_cnt;
    if (tid == 0) s_cnt = 0;
    __syncthreads();

    // ---- y/z cull over this bh strip's precomputed list ----
    const int scnt = g_strip_cnt[bh];
    const unsigned short* slist = g_strip + bh * STRIDE_STRIP;
    for (int k = tid; k < scnt; k += THREADS) {
        const int g = slist[k];
        const float4 v0 = __ldg((const float4*)(g_rec + g * 12));      // mu, rx
        const float4 v1 = __ldg((const float4*)(g_rec + g * 12) + 1);  // ry,rz,a00,a01
        if (fabsf(bcy - v0.y) <= BH + v1.x &&
            fabsf(2.2f - v0.z) <= BHZ + v1.y) {
            s_list[atomicAdd(&s_cnt, 1)] = (unsigned short)g;
        }
    }
    __syncthreads();
    const int cnt = s_cnt;

    // smem staging: s_rec rows of 12 floats (3 float4), s_ft rows of 20 (5 float4).
    // Pool sized TILE*36 floats = 9216 B: staging uses the first 2048 floats,
    // and the cross-half reduction buffer needs the full 128*9 u64 = 9216 B.
    __shared__ __align__(16) float s_pool[TILE * 36];
    float* const s_rec = s_pool;                 // [TILE][12]
    float* const s_ft  = s_pool + TILE * 12;     // [TILE][20]

    uint64_t acc2[9];
    #pragma unroll
    for (int c = 0; c < 9; c++) acc2[c] = 0ull;

    for (int t0 = 0; t0 < cnt; t0 += TILE) {
        const int n = min(TILE, cnt - t0);

        // ---- copy staging: 8 float4 per entry, spread over all threads ----
        for (int i = tid; i < 8 * n; i += THREADS) {
            const int e = i >> 3;
            const int wd = i & 7;
            const int g = s_list[t0 + e];
            if (wd < 3) {
                ((float4*)(s_rec + e * 12))[wd] =
                    __ldg((const float4*)(g_rec + g * 12) + wd);
            } else {
                ((float4*)(s_ft + e * 20))[wd - 3] =
                    __ldg((const float4*)(g_ft + g * 20) + (wd - 3));
            }
        }
        __syncthreads();

        // ---- eval: straight predicated loop, packed f32x2 accumulation ----
        const int nh = (n + 1) >> 1;
        const int lo = half * nh;
        const int hi = min(n, lo + nh);
        #pragma unroll 2
        for (int j = lo; j < hi; j++) {
            const float4 v0 = *(const float4*)(s_rec + j * 12);      // mu, rx
            const float4 v1 = *(const float4*)(s_rec + j * 12 + 4);  // ry,rz,a00,a01
            const float4 v2 = *(const float4*)(s_rec + j * 12 + 8);  // a02,a11,a12,a22
            const float dx = px - v0.x;
            const float dy = py - v0.y;
            const float dz = pz - v0.z;
            const bool m = (fabsf(dx) <= v0.w) & (fabsf(dy) <= v1.x) &
                           (fabsf(dz) <= v1.y);
            float t1 = fmaf(v1.w, dy, v1.z * dx);        // a00 dx + a01 dy
            t1 = fmaf(v2.x, dz, t1);                     // + a02 dz
            const float t2 = fmaf(v2.z, dz, v2.y * dy);  // a11 dy + a12 dz
            float arg = v2.w * dz * dz;                  // a22 dz^2
            arg = fmaf(dy, t2, arg);
            arg = fmaf(dx, t1, arg);
            const float wgt = m ? __expf(arg) : 0.f;
            uint64_t w2;
            asm("mov.b64 %0, {%1, %1};" : "=l"(w2) : "f"(wgt));
            const uint64_t* f8 = (const uint64_t*)(s_ft + j * 20);
            #pragma unroll
            for (int q = 0; q < 4; q++) {
                const ulonglong2 fv = ((const ulonglong2*)f8)[q];
                ffma2(acc2[2 * q + 0], fv.x, w2);
                ffma2(acc2[2 * q + 1], fv.y, w2);
            }
            ffma2(acc2[8], f8[8], w2);
        }
        __syncthreads();
    }

    // ---- cross-half reduction through the (now dead) staging pool ----
    uint64_t* const red = (uint64_t*)s_pool;   // 128 rows x 9 u64 = 9216 B, fits
    if (half == 1) {
        uint64_t* r = red + pt * 9;
        #pragma unroll
        for (int c = 0; c < 9; c++) r[c] = acc2[c];
    }
    __syncthreads();
    if (half == 0) {
        const uint64_t* r = red + pt * 9;
        out[p] = 0.f;   // grid_density
        uint64_t* o = (uint64_t*)(out + NPTS + (size_t)p * NC);
        #pragma unroll
        for (int c = 0; c < 9; c++)
            o[c] = fadd2(acc2[c], r[c]);
    }
}

extern "C" void kernel_launch(void* const* d_in, const int* in_sizes, int n_in,
                              void* d_out, int out_size) {
    const float* means        = (const float*)d_in[0];
    const float* opacities    = (const float*)d_in[1];
    const float* scales       = (const float*)d_in[2];
    const float* rotations    = (const float*)d_in[3];
    const float* features     = (const float*)d_in[4];
    const float* empty_scalar = (const float*)d_in[5];
    float* out = (float*)d_out;

    precompute<<<34, 128>>>(means, opacities, scales, rotations,
                            features, empty_scalar);
    dim3 grid(25, 25);
    voxelize<<<grid, THREADS>>>(out);
}

// round 11
// speedup vs baseline: 1.3137x; 1.3137x over previous
#include <cuda_runtime.h>
#include <cuda_bf16.h>
#include <cstdint>

#define NPTS 80000          // 100*100*8
#define NG 1025             // 1024 gaussians + 1 synthetic "empty"
#define NC 18
#define THREADS 256
#define TILE 128

// Block tile: 4h x 4w x 8d = 128 points. 2 threads per point (gaussian-split).
// pt = tid & 127: dd = pt&7, ww = (pt>>3)&3, hh = pt>>5. half = tid>>7.

__device__ __forceinline__ void ffma2(uint64_t& acc, uint64_t ab, uint64_t w2) {
    asm("fma.rn.f32x2 %0, %1, %2, %0;" : "+l"(acc) : "l"(ab), "l"(w2));
}
__device__ __forceinline__ uint64_t fadd2(uint64_t a, uint64_t b) {
    uint64_t r;
    asm("add.rn.f32x2 %0, %1, %2;" : "=l"(r) : "l"(a), "l"(b));
    return r;
}

__global__ __launch_bounds__(THREADS, 5) void voxelize(
    const float* __restrict__ means,
    const float* __restrict__ opac,
    const float* __restrict__ scales,
    const float* __restrict__ rots,
    const float* __restrict__ feats,
    const float* __restrict__ empty_scalar,
    float* __restrict__ out)
{
    const int tid = threadIdx.x;
    const int pt = tid & 127;
    const int half = tid >> 7;
    const int bh = blockIdx.x, bw = blockIdx.y;
    const int dd = pt & 7;
    const int ww = (pt >> 3) & 3;
    const int hh = pt >> 5;
    const int h = 4 * bh + hh;
    const int w = 4 * bw + ww;
    const int p = h * 800 + w * 8 + dd;

    // match reference rounding: (i+0.5)*0.8 + lo, no fma contraction
    const float px = __fadd_rn(__fmul_rn((float)h + 0.5f, 0.8f), -40.f);
    const float py = __fadd_rn(__fmul_rn((float)w + 0.5f, 0.8f), -40.f);
    const float pz = __fadd_rn(__fmul_rn((float)dd + 0.5f, 0.8f), -1.f);

    // analytic block bbox (conservative, eps-padded); z center 2.2, half 2.8
    const float EPS = 1e-3f;
    const float bcx = (4.f * (float)bh + 2.f) * 0.8f - 40.f;   // half 1.2
    const float bcy = (4.f * (float)bw + 2.f) * 0.8f - 40.f;   // half 1.2
    const float BH  = 1.2f + EPS;
    const float BHZ = 2.8f + EPS;

    __shared__ unsigned short s_list[NG + 1];
    __shared__ int s_cnt;
    if (tid == 0) s_cnt = 0;
    __syncthreads();

    // ---- block-level compaction (4 unrolled iters, 24 LDGs in flight) ----
    {
        float mx[4], my[4], mz[4], sx[4], sy[4], sz[4];
        #pragma unroll
        for (int it = 0; it < 4; it++) {
            const int g = tid + it * 256;          // < 1024 always
            mx[it] = __ldg(means + 3 * g);
            my[it] = __ldg(means + 3 * g + 1);
            mz[it] = __ldg(means + 3 * g + 2);
            sx[it] = __ldg(scales + 3 * g);
            sy[it] = __ldg(scales + 3 * g + 1);
            sz[it] = __ldg(scales + 3 * g + 2);
        }
        #pragma unroll
        for (int it = 0; it < 4; it++) {
            const int g = tid + it * 256;
            if (fabsf(bcx - mx[it]) <= BH + 3.f * sx[it] &&
                fabsf(bcy - my[it]) <= BH + 3.f * sy[it] &&
                fabsf(2.2f - mz[it]) <= BHZ + 3.f * sz[it]) {
                s_list[atomicAdd(&s_cnt, 1)] = (unsigned short)g;
            }
        }
        if (tid == 0)   // synthetic gaussian covers the whole volume: always in
            s_list[atomicAdd(&s_cnt, 1)] = (unsigned short)(NG - 1);
    }
    __syncthreads();
    const int cnt = s_cnt;

    // rec layout (12 floats/row, 3x LDS.128):
    //   [0..2]=mu [3]=rx | [4]=ry [5]=rz [6]=a00 [7]=a01 | [8]=a02 [9]=a11 [10]=a12 [11]=a22
    // a_ij carry -0.5 and off-diagonal 2x folded in:
    //   arg = a00 dx^2 + a11 dy^2 + a22 dz^2 + a01 dxdy + a02 dxdz + a12 dydz
    // feature rows carry opacity folded in: staged_f = opa * f.
    // s_pool: [0, TILE*12) = s_rec; [TILE*12, TILE*32) = s_ft rows of 20.
    // After the loop the pool (4096 floats >= 128*18) is the reduction buffer.
    __shared__ __align__(16) float s_pool[TILE * 32];
    float* const s_rec = s_pool;                 // [TILE][12]
    float* const s_ft  = s_pool + TILE * 12;     // [TILE][20]

    uint64_t acc2[9];
    #pragma unroll
    for (int c = 0; c < 9; c++) acc2[c] = 0ull;

    for (int t0 = 0; t0 < cnt; t0 += TILE) {
        const int n = min(TILE, cnt - t0);

        // ---- dense staging: tid<n -> record; 128<=tid<128+n -> features ----
        if (tid < n) {
            const int g = s_list[t0 + tid];
            float* rc = s_rec + tid * 12;
            if (g < NG - 1) {
                float qw = __ldg(rots + g * 4 + 0), qx = __ldg(rots + g * 4 + 1);
                float qy = __ldg(rots + g * 4 + 2), qz = __ldg(rots + g * 4 + 3);
                float inv = rsqrtf(qw * qw + qx * qx + qy * qy + qz * qz);
                qw *= inv; qx *= inv; qy *= inv; qz *= inv;
                float R00 = 1.f - 2.f * (qy * qy + qz * qz);
                float R01 = 2.f * (qx * qy - qw * qz);
                float R02 = 2.f * (qx * qz + qw * qy);
                float R10 = 2.f * (qx * qy + qw * qz);
                float R11 = 1.f - 2.f * (qx * qx + qz * qz);
                float R12 = 2.f * (qy * qz - qw * qx);
                float R20 = 2.f * (qx * qz - qw * qy);
                float R21 = 2.f * (qy * qz + qw * qx);
                float R22 = 1.f - 2.f * (qx * qx + qy * qy);

                float s0 = __ldg(scales + g * 3 + 0);
                float s1 = __ldg(scales + g * 3 + 1);
                float s2 = __ldg(scales + g * 3 + 2);
                float s0q = s0 * s0, s1q = s1 * s1, s2q = s2 * s2;

                float a  = s0q * R00 * R00 + s1q * R01 * R01 + s2q * R02 * R02;
                float b  = s0q * R00 * R10 + s1q * R01 * R11 + s2q * R02 * R12;
                float c  = s0q * R00 * R20 + s1q * R01 * R21 + s2q * R02 * R22;
                float dd_ = s0q * R10 * R10 + s1q * R11 * R11 + s2q * R12 * R12;
                float e  = s0q * R10 * R20 + s1q * R11 * R21 + s2q * R12 * R22;
                float f  = s0q * R20 * R20 + s1q * R21 * R21 + s2q * R22 * R22;

                float det = a * (dd_ * f - e * e) - b * (b * f - e * c) + c * (b * e - dd_ * c);
                float idet = 1.0f / det;

                rc[0] = __ldg(means + g * 3 + 0);
                rc[1] = __ldg(means + g * 3 + 1);
                rc[2] = __ldg(means + g * 3 + 2);
                rc[3] = 3.f * s0;
                rc[4] = 3.f * s1;
                rc[5] = 3.f * s2;
                rc[6]  = -0.5f * (dd_ * f - e * e) * idet;   // a00
                rc[7]  = -(c * e - b * f) * idet;            // a01 (2x folded)
                rc[8]  = -(b * e - c * dd_) * idet;          // a02
                rc[9]  = -0.5f * (a * f - c * c) * idet;     // a11
                rc[10] = -(b * c - a * e) * idet;            // a12
                rc[11] = -0.5f * (a * dd_ - b * b) * idet;   // a22
            } else {
                rc[0] = 0.f; rc[1] = 0.f; rc[2] = 2.2f;
                rc[3] = 240.f; rc[4] = 240.f; rc[5] = 19.2f;
                rc[6]  = -0.5f / 6400.f;
                rc[7]  = 0.f; rc[8] = 0.f;
                rc[9]  = -0.5f / 6400.f;
                rc[10] = 0.f;
                rc[11] = -0.5f / 40.96f;
            }
        } else if (tid >= 128 && tid < 128 + n) {
            const int s = tid - 128;
            const int g = s_list[t0 + s];
            float* ft = s_ft + s * 20;
            if (g < NG - 1) {
                const float op = __ldg(opac + g);
                const float* fs = feats + (size_t)g * (NC - 1);
                #pragma unroll
                for (int c = 0; c < NC - 1; c++) ft[c] = op * __ldg(fs + c);
                ft[NC - 1] = 0.f;
            } else {
                #pragma unroll
                for (int c = 0; c < NC - 1; c++) ft[c] = 0.f;
                ft[NC - 1] = __ldg(empty_scalar);   // opa = 1
            }
        }
        __syncthreads();

        // ---- eval: straight predicated loop, packed f32x2 accumulation ----
        const int nh = (n + 1) >> 1;
        const int lo = half * nh;
        const int hi = min(n, lo + nh);
        #pragma unroll 2
        for (int j = lo; j < hi; j++) {
            const float4 v0 = *(const float4*)(s_rec + j * 12);      // mu, rx
            const float4 v1 = *(const float4*)(s_rec + j * 12 + 4);  // ry,rz,a00,a01
            const float4 v2 = *(const float4*)(s_rec + j * 12 + 8);  // a02,a11,a12,a22
            const float dx = px - v0.x;
            const float dy = py - v0.y;
            const float dz = pz - v0.z;
            const bool m = (fabsf(dx) <= v0.w) & (fabsf(dy) <= v1.x) &
                           (fabsf(dz) <= v1.y);
            float t1 = fmaf(v1.w, dy, v1.z * dx);        // a00 dx + a01 dy
            t1 = fmaf(v2.x, dz, t1);                     // + a02 dz
            const float t2 = fmaf(v2.z, dz, v2.y * dy);  // a11 dy + a12 dz
            float arg = v2.w * dz * dz;                  // a22 dz^2
            arg = fmaf(dy, t2, arg);
            arg = fmaf(dx, t1, arg);
            const float wgt = m ? __expf(arg) : 0.f;
            uint64_t w2;
            asm("mov.b64 %0, {%1, %1};" : "=l"(w2) : "f"(wgt));
            const uint64_t* f8 = (const uint64_t*)(s_ft + j * 20);
            #pragma unroll
            for (int q = 0; q < 4; q++) {
                const ulonglong2 fv = ((const ulonglong2*)f8)[q];
                ffma2(acc2[2 * q + 0], fv.x, w2);
                ffma2(acc2[2 * q + 1], fv.y, w2);
            }
            ffma2(acc2[8], f8[8], w2);
        }
        __syncthreads();
    }

    // ---- cross-half reduction through the (now dead) staging pool ----
    uint64_t* const red = (uint64_t*)s_pool;   // 128 rows x 9 u64 = 9216 B, fits
    if (half == 1) {
        uint64_t* r = red + pt * 9;
        #pragma unroll
        for (int c = 0; c < 9; c++) r[c] = acc2[c];
    }
    __syncthreads();
    if (half == 0) {
        const uint64_t* r = red + pt * 9;
        out[p] = 0.f;   // grid_density
        uint64_t* o = (uint64_t*)(out + NPTS + (size_t)p * NC);
        #pragma unroll
        for (int c = 0; c < 9; c++)
            o[c] = fadd2(acc2[c], r[c]);
    }
}

extern "C" void kernel_launch(void* const* d_in, const int* in_sizes, int n_in,
                              void* d_out, int out_size) {
    const float* means        = (const float*)d_in[0];
    const float* opacities    = (const float*)d_in[1];
    const float* scales       = (const float*)d_in[2];
    const float* rotations    = (const float*)d_in[3];
    const float* features     = (const float*)d_in[4];
    const float* empty_scalar = (const float*)d_in[5];
    float* out = (float*)d_out;

    dim3 grid(25, 25);
    voxelize<<<grid, THREADS>>>(means, opacities, scales, rotations,
                                features, empty_scalar, out);
}